// round 1
// baseline (speedup 1.0000x reference)
#include <cuda_runtime.h>
#include <math.h>

// Problem constants
#define Bdim 8
#define Ndim 256
#define Ddim 128
#define K2   256   // 2*D
#define MI   16    // i-tile
#define MJ   8     // j-tile  (MI*MJ = 128 pairs per CTA)
#define NP   128   // pairs per CTA
#define NDo  128   // output channels (D)
#define KC   16    // K chunk

// Scratch for the per-node projections (allocation-free rule -> device globals)
__device__ float g_Pi[Bdim * Ndim * K2];   // Pi + b1 folded in
__device__ float g_Pj[Bdim * Ndim * K2];

// ---------------------------------------------------------------------------
// Kernel 1: Pi = x@W1a + x_next@W1b + b1 ; Pj = x@W1c + x_next@W1d
// grid: (B, N/8), 256 threads. Each CTA does 8 consecutive n rows of one batch,
// reusing each W1 element for 8 rows.
// ---------------------------------------------------------------------------
__global__ void __launch_bounds__(256) proj_kernel(
    const float* __restrict__ x,     // [B,N,D]
    const float* __restrict__ W1,    // [512,256] row-major
    const float* __restrict__ b1,    // [256]
    float* __restrict__ outTour,     // [B,N] as float (or unused)
    int hasTour)
{
    __shared__ float xr[9][128];     // rows n0..n0+8 (wrap)
    const int b  = blockIdx.x;
    const int n0 = blockIdx.y * 8;
    const int tid = threadIdx.x;

    for (int idx = tid; idx < 9 * 128; idx += 256) {
        int r = idx >> 7, c = idx & 127;
        int n = (n0 + r) & (Ndim - 1);
        xr[r][c] = x[((b * Ndim) + n) * Ddim + c];
    }
    __syncthreads();

    const int c = tid;  // output channel 0..255
    float accPi[8], accPj[8];
#pragma unroll
    for (int r = 0; r < 8; r++) { accPi[r] = 0.f; accPj[r] = 0.f; }

    for (int k = 0; k < 128; k++) {
        float wa = W1[(k        ) * 256 + c];
        float wb = W1[(k + 128  ) * 256 + c];
        float wc = W1[(k + 256  ) * 256 + c];
        float wd = W1[(k + 384  ) * 256 + c];
#pragma unroll
        for (int r = 0; r < 8; r++) {
            float xi = xr[r][k];
            float xn = xr[r + 1][k];
            accPi[r] = fmaf(xi, wa, accPi[r]);
            accPi[r] = fmaf(xn, wb, accPi[r]);
            accPj[r] = fmaf(xi, wc, accPj[r]);
            accPj[r] = fmaf(xn, wd, accPj[r]);
        }
    }
    const float bias = b1[c];
#pragma unroll
    for (int r = 0; r < 8; r++) {
        int n = n0 + r;
        g_Pi[((b * Ndim) + n) * K2 + c] = accPi[r] + bias;
        g_Pj[((b * Ndim) + n) * K2 + c] = accPj[r];
    }
    if (hasTour && tid < 8) {
        outTour[b * Ndim + n0 + tid] = (float)(n0 + tid);
    }
}

// ---------------------------------------------------------------------------
// Kernel 2: per (b, i-tile, j-tile):
//   A[p,k] = relu(Pi[i,k] + Pj[j,k])   (built per K-chunk in SMEM)
//   H[p,d] = relu(A @ W2 + b2)         (register-blocked 8x8 per thread)
//   score  = tanh(H @ W3 + b3), masked, written to out matrix
// Threads: 256 as (tp = tid&15 pair-group, td = tid>>4 d-group), 8x8 acc each.
// SMEM: Pi tile 16x256, Pj tile 8x256, W2 full 256x128, A chunk 16x(128+4),
//       reduction 128x17  -> 172800 B total.
// ---------------------------------------------------------------------------
#define SM_PI   0
#define SM_PJ   (SM_PI + MI * K2)          // 4096
#define SM_W2   (SM_PJ + MJ * K2)          // 6144
#define SM_A    (SM_W2 + K2 * NDo)         // 38912
#define A_STRIDE 132
#define SM_RED  (SM_A + KC * A_STRIDE)     // 41024
#define RED_STRIDE 17
#define SM_FLOATS (SM_RED + NP * RED_STRIDE)  // 43200 floats = 172800 B

__global__ void __launch_bounds__(256) pair_kernel(
    const float* __restrict__ W2g,   // [256,128]
    const float* __restrict__ b2g,   // [128]
    const float* __restrict__ W3g,   // [128]
    const float* __restrict__ b3g,   // [1]
    float* __restrict__ outM)        // [B,N,N]
{
    extern __shared__ float sm[];
    const int bj = blockIdx.x;
    const int bi = blockIdx.y;
    const int b  = blockIdx.z;
    const int i0 = bi * MI;
    const int j0 = bj * MJ;
    const int tid = threadIdx.x;

    // Fully-masked tile (valid needs j >= i+2): skip compute, write zeros.
    if (j0 + MJ - 1 < i0 + 2) {
        if (tid < NP) {
            int pi = tid >> 3, pj = tid & 7;
            outM[(b * Ndim + i0 + pi) * Ndim + (j0 + pj)] = 0.f;
        }
        return;
    }

    float* sPi = sm + SM_PI;
    float* sPj = sm + SM_PJ;
    float* sW2 = sm + SM_W2;
    float* sA  = sm + SM_A;
    float* sRed = sm + SM_RED;

    // --- load tiles (float4) ---
    {
        const float4* gPi4 = (const float4*)(g_Pi + ((size_t)(b * Ndim + i0)) * K2);
        float4* sPi4 = (float4*)sPi;
        for (int idx = tid; idx < MI * K2 / 4; idx += 256) sPi4[idx] = gPi4[idx];

        const float4* gPj4 = (const float4*)(g_Pj + ((size_t)(b * Ndim + j0)) * K2);
        float4* sPj4 = (float4*)sPj;
        for (int idx = tid; idx < MJ * K2 / 4; idx += 256) sPj4[idx] = gPj4[idx];

        const float4* gW2 = (const float4*)W2g;
        float4* sW24 = (float4*)sW2;
        for (int idx = tid; idx < K2 * NDo / 4; idx += 256) sW24[idx] = gW2[idx];
    }
    __syncthreads();

    const int tp = tid & 15;   // pair group: pairs tp*8 .. tp*8+7
    const int td = tid >> 4;   // d group:    d td*8 .. td*8+7

    float acc[8][8];
#pragma unroll
    for (int r = 0; r < 8; r++)
#pragma unroll
        for (int c = 0; c < 8; c++) acc[r][c] = 0.f;

    for (int kb = 0; kb < K2 / KC; kb++) {
        const int k0 = kb * KC;
        // build A chunk: A[kk][p] = relu(Pi[pi][k0+kk] + Pj[pj][k0+kk])
#pragma unroll
        for (int t = 0; t < 8; t++) {
            int idx = t * 256 + tid;            // 0..2047
            int p  = idx >> 4;                  // 0..127
            int kk = idx & 15;
            int pi = p >> 3, pj = p & 7;
            float v = sPi[pi * K2 + k0 + kk] + sPj[pj * K2 + k0 + kk];
            sA[kk * A_STRIDE + p] = fmaxf(v, 0.f);
        }
        __syncthreads();

#pragma unroll
        for (int kk = 0; kk < KC; kk++) {
            float4 a0 = *(const float4*)&sA[kk * A_STRIDE + tp * 8];
            float4 a1 = *(const float4*)&sA[kk * A_STRIDE + tp * 8 + 4];
            float4 w0 = *(const float4*)&sW2[(k0 + kk) * NDo + td * 8];
            float4 w1 = *(const float4*)&sW2[(k0 + kk) * NDo + td * 8 + 4];
            float av[8] = {a0.x, a0.y, a0.z, a0.w, a1.x, a1.y, a1.z, a1.w};
            float wv[8] = {w0.x, w0.y, w0.z, w0.w, w1.x, w1.y, w1.z, w1.w};
#pragma unroll
            for (int r = 0; r < 8; r++)
#pragma unroll
                for (int c = 0; c < 8; c++)
                    acc[r][c] = fmaf(av[r], wv[c], acc[r][c]);
        }
        __syncthreads();
    }

    // --- epilogue: relu(+b2), dot with W3, cross-thread reduce, tanh, mask ---
    float b2v[8], w3v[8];
#pragma unroll
    for (int c = 0; c < 8; c++) {
        int d = td * 8 + c;
        b2v[c] = b2g[d];
        w3v[c] = W3g[d];
    }
    const float b3v = b3g[0];

#pragma unroll
    for (int r = 0; r < 8; r++) {
        float s = 0.f;
#pragma unroll
        for (int c = 0; c < 8; c++) {
            float h = fmaxf(acc[r][c] + b2v[c], 0.f);
            s = fmaf(h, w3v[c], s);
        }
        sRed[(tp * 8 + r) * RED_STRIDE + td] = s;
    }
    __syncthreads();

    if (tid < NP) {
        float s = 0.f;
#pragma unroll
        for (int t = 0; t < 16; t++) s += sRed[tid * RED_STRIDE + t];
        float val = tanhf(s + b3v);
        int pi = tid >> 3, pj = tid & 7;
        int i = i0 + pi, j = j0 + pj;
        bool valid = (j >= i + 2) && ((j - i) != (Ndim - 1));
        outM[(b * Ndim + i) * Ndim + j] = valid ? val : 0.f;
    }
}

// ---------------------------------------------------------------------------
extern "C" void kernel_launch(void* const* d_in, const int* in_sizes, int n_in,
                              void* d_out, int out_size) {
    const float* x  = (const float*)d_in[0];   // tour_features [8,256,128]
    const float* W1 = (const float*)d_in[1];   // [512,256]
    const float* b1 = (const float*)d_in[2];   // [256]
    const float* W2 = (const float*)d_in[3];   // [256,128]
    const float* b2 = (const float*)d_in[4];   // [128]
    const float* W3 = (const float*)d_in[5];   // [128,1]
    const float* b3 = (const float*)d_in[6];   // [1]

    float* out = (float*)d_out;
    // Output contract: reference returns (improved_tour [B,N], matrix [B,N,N]).
    // Adapt to whatever out_size says.
    const int matElems  = Bdim * Ndim * Ndim;
    const int tourElems = Bdim * Ndim;
    int hasTour = (out_size >= matElems + tourElems) ? 1 : 0;
    float* outTour = out;
    float* outM    = hasTour ? (out + tourElems) : out;

    cudaFuncSetAttribute(pair_kernel, cudaFuncAttributeMaxDynamicSharedMemorySize,
                         SM_FLOATS * (int)sizeof(float));

    dim3 g1(Bdim, Ndim / 8);
    proj_kernel<<<g1, 256>>>(x, W1, b1, outTour, hasTour);

    dim3 g2(Ndim / MJ, Ndim / MI, Bdim);
    pair_kernel<<<g2, 256, SM_FLOATS * sizeof(float)>>>(W2, b2, W3, b3, outM);
}

// round 3
// speedup vs baseline: 3.9572x; 3.9572x over previous
#include <cuda_runtime.h>
#include <math.h>
#include <stdint.h>

#define Bdim 8
#define Ndim 256
#define Ddim 128
#define K2   256

// Scratch for per-node projections (allocation-free rule -> device globals)
__device__ float g_Pi[Bdim * Ndim * K2];
__device__ float g_Pj[Bdim * Ndim * K2];

// ---------------------------------------------------------------------------
// Kernel 1 (proven): Pi = x@W1a + x_next@W1b + b1 ; Pj = x@W1c + x_next@W1d
// ---------------------------------------------------------------------------
__global__ void __launch_bounds__(256) proj_kernel(
    const float* __restrict__ x, const float* __restrict__ W1,
    const float* __restrict__ b1, float* __restrict__ outTour, int hasTour)
{
    __shared__ float xr[9][128];
    const int b  = blockIdx.x;
    const int n0 = blockIdx.y * 8;
    const int tid = threadIdx.x;

    for (int idx = tid; idx < 9 * 128; idx += 256) {
        int r = idx >> 7, c = idx & 127;
        int n = (n0 + r) & (Ndim - 1);
        xr[r][c] = x[((b * Ndim) + n) * Ddim + c];
    }
    __syncthreads();

    const int c = tid;
    float accPi[8], accPj[8];
#pragma unroll
    for (int r = 0; r < 8; r++) { accPi[r] = 0.f; accPj[r] = 0.f; }

    for (int k = 0; k < 128; k++) {
        float wa = W1[(k      ) * 256 + c];
        float wb = W1[(k + 128) * 256 + c];
        float wc = W1[(k + 256) * 256 + c];
        float wd = W1[(k + 384) * 256 + c];
#pragma unroll
        for (int r = 0; r < 8; r++) {
            float xi = xr[r][k];
            float xn = xr[r + 1][k];
            accPi[r] = fmaf(xi, wa, accPi[r]);
            accPi[r] = fmaf(xn, wb, accPi[r]);
            accPj[r] = fmaf(xi, wc, accPj[r]);
            accPj[r] = fmaf(xn, wd, accPj[r]);
        }
    }
    const float bias = b1[c];
#pragma unroll
    for (int r = 0; r < 8; r++) {
        int n = n0 + r;
        g_Pi[((b * Ndim) + n) * K2 + c] = accPi[r] + bias;
        g_Pj[((b * Ndim) + n) * K2 + c] = accPj[r];
    }
    if (hasTour && tid < 8) outTour[b * Ndim + n0 + tid] = (float)(n0 + tid);
}

// ---------------------------------------------------------------------------
// mma.sync m16n8k8 tf32 helper (sm_80+ feature -> valid on compute_103)
// ---------------------------------------------------------------------------
__device__ __forceinline__ void mma_tf32(float* d, const uint32_t* a,
                                         const uint32_t* b) {
    asm volatile(
        "mma.sync.aligned.m16n8k8.row.col.f32.tf32.tf32.f32 "
        "{%0,%1,%2,%3},{%4,%5,%6,%7},{%8,%9},{%0,%1,%2,%3};\n"
        : "+f"(d[0]), "+f"(d[1]), "+f"(d[2]), "+f"(d[3])
        : "r"(a[0]), "r"(a[1]), "r"(a[2]), "r"(a[3]), "r"(b[0]), "r"(b[1]));
}

// ---------------------------------------------------------------------------
// SMEM layout (floats). Strides padded for conflict-free fragment loads.
// ---------------------------------------------------------------------------
#define W2S 136                      // W2 [256][128] stored stride 136
#define PIS 260                      // Pi/Pj rows stride 260
#define OFF_W2  0                    // 256*136      = 34816
#define OFF_PI  34816                // 16*260       =  4160
#define OFF_PJ  (OFF_PI + 16*PIS)    // 38976; 8*260 =  2080
#define OFF_B2  (OFF_PJ + 8*PIS)     // 41056
#define OFF_W3  (OFF_B2 + 128)       // 41184
#define OFF_RED (OFF_W3 + 128)       // 41312; 256 floats
#define SMEM_FLOATS (OFF_RED + 256)  // 41568 -> 166272 bytes
#define SMEM_BYTES (SMEM_FLOATS * 4)

#define NTILES_PER_B 272
#define NTILES_TOT   (Bdim * NTILES_PER_B)   // 2176
#define GRID_PAIR    152

// ---------------------------------------------------------------------------
// Kernel 2: persistent mma.sync tf32 pair kernel.
// CTA tile: M=128 pairs (16 i x 8 j), N=128 outs, K=256.
// 8 warps: wid>>1 = M-split (32 rows), wid&1 = N-split (64 cols).
// ---------------------------------------------------------------------------
__global__ void __launch_bounds__(256, 1) pair_mma_kernel(
    const float* __restrict__ W2g, const float* __restrict__ b2g,
    const float* __restrict__ W3g, const float* __restrict__ b3g,
    float* __restrict__ outM)
{
    extern __shared__ float sm[];
    float* sW2 = sm + OFF_W2;
    float* sPi = sm + OFF_PI;
    float* sPj = sm + OFF_PJ;
    float* sB2 = sm + OFF_B2;
    float* sW3 = sm + OFF_W3;
    float* sRed = sm + OFF_RED;

    const int tid  = threadIdx.x;
    const int wid  = tid >> 5;
    const int lane = tid & 31;
    const int q = lane >> 2;     // group id
    const int c = lane & 3;      // thread-in-group

    // Load W2 [k][n] -> smem stride 136
    for (int idx = tid; idx < 256 * 32; idx += 256) {
        int k = idx >> 5, n0 = (idx & 31) << 2;
        *(float4*)(sW2 + k * W2S + n0) = *(const float4*)(W2g + k * 128 + n0);
    }
    if (tid < 128) { sB2[tid] = b2g[tid]; sW3[tid] = W3g[tid]; }
    const float b3v = b3g[0];
    __syncthreads();

    const int mb = (wid >> 1) * 32;   // warp's M base (pair rows)
    const int nb = (wid & 1) * 64;    // warp's N base (output cols)

    // A-fragment row indices: rows mb+q (+8, +16, +24); i_local = row>>3,
    // j_local = row&7 = q for all four.
    const float* piR0 = sPi + ((mb >> 3) + 0) * PIS;  // rows mb+q      (am=0 a0/a2)
    const float* piR1 = sPi + ((mb >> 3) + 1) * PIS;  // rows mb+q+8    (am=0 a1/a3)
    const float* piR2 = sPi + ((mb >> 3) + 2) * PIS;  // rows mb+q+16   (am=1 a0/a2)
    const float* piR3 = sPi + ((mb >> 3) + 3) * PIS;  // rows mb+q+24
    const float* pjR  = sPj + q * PIS;

    for (int t = blockIdx.x; t < NTILES_TOT; t += gridDim.x) {
        // map t -> (batch, bi, bj); valid tiles: bj >= 2*bi
        int b = t / NTILES_PER_B;
        int r = t - b * NTILES_PER_B;
        int bi = 0;
        while (r >= 32 - 2 * bi) { r -= 32 - 2 * bi; bi++; }
        const int bj = 2 * bi + r;
        const int i0 = bi * 16, j0 = bj * 8;

        // stage Pi (16x256) / Pj (8x256) into padded smem
        {
            const float* gPi = g_Pi + (size_t)(b * Ndim + i0) * K2;
            const float* gPj = g_Pj + (size_t)(b * Ndim + j0) * K2;
            for (int idx = tid; idx < 16 * 64; idx += 256) {
                int row = idx >> 6, k4 = (idx & 63) << 2;
                *(float4*)(sPi + row * PIS + k4) = *(const float4*)(gPi + row * 256 + k4);
            }
            for (int idx = tid; idx < 8 * 64; idx += 256) {
                int row = idx >> 6, k4 = (idx & 63) << 2;
                *(float4*)(sPj + row * PIS + k4) = *(const float4*)(gPj + row * 256 + k4);
            }
        }
        __syncthreads();

        float acc[2][8][4];
#pragma unroll
        for (int am = 0; am < 2; am++)
#pragma unroll
            for (int a = 0; a < 8; a++)
#pragma unroll
                for (int e = 0; e < 4; e++) acc[am][a][e] = 0.f;

        for (int k0 = 0; k0 < 256; k0 += 8) {
            const int k1 = k0 + c, k2 = k0 + c + 4;

            // B fragments: b0 = W2[k1][n], b1 = W2[k2][n], n = nb + 8a + q
            uint32_t bf[8][2];
#pragma unroll
            for (int a = 0; a < 8; a++) {
                bf[a][0] = __float_as_uint(sW2[k1 * W2S + nb + 8 * a + q]);
                bf[a][1] = __float_as_uint(sW2[k2 * W2S + nb + 8 * a + q]);
            }

            // Shared Pj values (j depends only on q)
            const float pj1 = pjR[k1], pj2 = pjR[k2];

            // A fragments, M-atom 0 (rows mb+q, mb+q+8)
            {
                uint32_t af[4];
                af[0] = __float_as_uint(fmaxf(piR0[k1] + pj1, 0.f));
                af[1] = __float_as_uint(fmaxf(piR1[k1] + pj1, 0.f));
                af[2] = __float_as_uint(fmaxf(piR0[k2] + pj2, 0.f));
                af[3] = __float_as_uint(fmaxf(piR1[k2] + pj2, 0.f));
#pragma unroll
                for (int a = 0; a < 8; a++) mma_tf32(acc[0][a], af, bf[a]);
            }
            // A fragments, M-atom 1 (rows mb+q+16, mb+q+24)
            {
                uint32_t af[4];
                af[0] = __float_as_uint(fmaxf(piR2[k1] + pj1, 0.f));
                af[1] = __float_as_uint(fmaxf(piR3[k1] + pj1, 0.f));
                af[2] = __float_as_uint(fmaxf(piR2[k2] + pj2, 0.f));
                af[3] = __float_as_uint(fmaxf(piR3[k2] + pj2, 0.f));
#pragma unroll
                for (int a = 0; a < 8; a++) mma_tf32(acc[1][a], af, bf[a]);
            }
        }

        // epilogue: h = relu(acc + b2[n]); s = sum_n h*w3[n]; rows reduce
#pragma unroll
        for (int am = 0; am < 2; am++) {
            float s0 = 0.f, s1 = 0.f;   // rows mb+am*16+q and +8
#pragma unroll
            for (int a = 0; a < 8; a++) {
                int n0 = nb + 8 * a + 2 * c;
                float w0 = sW3[n0], w1 = sW3[n0 + 1];
                float bb0 = sB2[n0], bb1 = sB2[n0 + 1];
                s0 = fmaf(fmaxf(acc[am][a][0] + bb0, 0.f), w0, s0);
                s0 = fmaf(fmaxf(acc[am][a][1] + bb1, 0.f), w1, s0);
                s1 = fmaf(fmaxf(acc[am][a][2] + bb0, 0.f), w0, s1);
                s1 = fmaf(fmaxf(acc[am][a][3] + bb1, 0.f), w1, s1);
            }
            // reduce over the 4 lanes sharing each row (lane&3)
            s0 += __shfl_xor_sync(0xffffffffu, s0, 1);
            s0 += __shfl_xor_sync(0xffffffffu, s0, 2);
            s1 += __shfl_xor_sync(0xffffffffu, s1, 1);
            s1 += __shfl_xor_sync(0xffffffffu, s1, 2);
            if (c == 0) {
                int m0 = mb + am * 16 + q;
                sRed[m0 * 2 + (wid & 1)]       = s0;
                sRed[(m0 + 8) * 2 + (wid & 1)] = s1;
            }
        }
        __syncthreads();

        if (tid < 128) {
            float s = sRed[tid * 2] + sRed[tid * 2 + 1];
            float val = tanhf(s + b3v);
            int i = i0 + (tid >> 3), j = j0 + (tid & 7);
            bool valid = (j >= i + 2) && ((j - i) != (Ndim - 1));
            outM[(b * Ndim + i) * Ndim + j] = valid ? val : 0.f;
        }
        // next-iteration staging is safe: the sync above guarantees every warp
        // finished its k-loop (sRed written post-k-loop) before sPi/sPj reuse.
    }
}

// ---------------------------------------------------------------------------
extern "C" void kernel_launch(void* const* d_in, const int* in_sizes, int n_in,
                              void* d_out, int out_size) {
    const float* x  = (const float*)d_in[0];
    const float* W1 = (const float*)d_in[1];
    const float* b1 = (const float*)d_in[2];
    const float* W2 = (const float*)d_in[3];
    const float* b2 = (const float*)d_in[4];
    const float* W3 = (const float*)d_in[5];
    const float* b3 = (const float*)d_in[6];

    float* out = (float*)d_out;
    const int matElems  = Bdim * Ndim * Ndim;
    const int tourElems = Bdim * Ndim;
    int hasTour = (out_size >= matElems + tourElems) ? 1 : 0;
    float* outTour = out;
    float* outM    = hasTour ? (out + tourElems) : out;

    // zero matrix region (covers fully-masked tiles); computed tiles overwrite
    cudaMemsetAsync(outM, 0, (size_t)matElems * sizeof(float), 0);

    dim3 g1(Bdim, Ndim / 8);
    proj_kernel<<<g1, 256>>>(x, W1, b1, outTour, hasTour);

    cudaFuncSetAttribute(pair_mma_kernel, cudaFuncAttributeMaxDynamicSharedMemorySize,
                         SMEM_BYTES);
    pair_mma_kernel<<<GRID_PAIR, 256, SMEM_BYTES>>>(W2, b2, W3, b3, outM);
}